// round 3
// baseline (speedup 1.0000x reference)
#include <cuda_runtime.h>
#include <cstdint>
#include <cstddef>

// Problem constants
#define N_E   1024
#define CDIM  256
#define NB    16
#define NH    64
#define NW    64
#define HW_   (NH*NW)        // 4096
#define NROWS (NB*HW_)       // 65536
#define COS_ELEMS (NB*NW*CDIM)  // 262144

// Output layout (float32): [cosine (B,W,C) | idx_gt (N) | idx (N)]
#define OFF_IDXGT COS_ELEMS
#define OFF_IDX   (COS_ELEMS + NROWS)

// Scratch (device globals: allocation-free rule)
__device__ float g_cbnorm[N_E];
__device__ float g_xnorm[2 * NROWS];

// ---------- packed f32x2 helpers (sm_100+) ----------
static __device__ __forceinline__ void upk2(float& lo, float& hi, unsigned long long v) {
    asm("mov.b64 {%0,%1}, %2;" : "=f"(lo), "=f"(hi) : "l"(v));
}
static __device__ __forceinline__ void fma2(unsigned long long& d,
                                            unsigned long long a,
                                            unsigned long long b) {
    asm("fma.rn.f32x2 %0, %1, %2, %3;" : "=l"(d) : "l"(a), "l"(b), "l"(d));
}

// ---------- XLA-row-reduce-emulating sum of squares over 256 elements ----------
// Reference (eager JAX) computes y = x*x (rounded separately), then
// jnp.sum(y, axis=1). XLA:GPU row reduction for a 256-wide f32 row:
// vector_size=2 -> thread t: pair_t = rn(y[2t] + y[2t+1]), 4 warps of 32,
// per-warp shfl tree (16,8,4,2,1), then cross-warp rn(rn(T0+T2)+rn(T1+T3)).
// We emulate with ONE warp: lane l computes pair_{32w+l} for w=0..3
// (i.e. c0 = 64w + 2l) and runs 4 independent butterfly trees (lane-0
// bracketing of xor-butterfly == shfl-down tree).
// 'stride' = element stride between consecutive c (1 for codebook,
// HW_ for the transposed z/gt view).
template <int STRIDE>
static __device__ __forceinline__ float xla_row_sumsq(const float* __restrict__ p, int lane) {
    float T[4];
#pragma unroll
    for (int w = 0; w < 4; w++) {
        int c0 = w * 64 + 2 * lane;
        float a = p[(size_t)c0 * STRIDE];
        float b = p[(size_t)(c0 + 1) * STRIDE];
        float v = __fadd_rn(__fmul_rn(a, a), __fmul_rn(b, b));
#pragma unroll
        for (int off = 16; off > 0; off >>= 1)
            v = __fadd_rn(v, __shfl_xor_sync(0xffffffffu, v, off));
        T[w] = v;
    }
    return __fadd_rn(__fadd_rn(T[0], T[2]), __fadd_rn(T[1], T[3]));
}

// ---------- kernel 1: codebook squared norms ----------
__global__ void cbnorm_kernel(const float* __restrict__ cb) {
    int warp = blockIdx.x * (blockDim.x >> 5) + (threadIdx.x >> 5);
    int lane = threadIdx.x & 31;
    if (warp >= N_E) return;
    float s = xla_row_sumsq<1>(cb + (size_t)warp * CDIM, lane);
    if (lane == 0) g_cbnorm[warp] = s;
}

// ---------- kernel 2: per-row ||x||^2 for z and gt ----------
// Row n: zf[n][c] = z[b, c, h, w], n = b*4096 + h*64 + w; element c at
// stride HW_. 32 consecutive rows per 1024-thread block so the strided
// lane loads coalesce across warps through L1 sectors.
__global__ __launch_bounds__(1024)
void xnorm_kernel(const float* __restrict__ z, const float* __restrict__ gt) {
    int wg   = blockIdx.x * 32 + (threadIdx.x >> 5);   // 0..131071
    int lane = threadIdx.x & 31;
    int src  = wg >> 16;
    int n    = wg & (NROWS - 1);
    int b    = n >> 12;
    int rem  = n & (HW_ - 1);
    const float* p = (src ? gt : z) + (size_t)b * CDIM * HW_ + rem;
    float s = xla_row_sumsq<HW_>(p, lane);
    if (lane == 0) g_xnorm[wg] = s;
}

// ---------- kernel 3: fused distance-GEMM + argmin ----------
// BM=128 rows x BN=128 codes per block, K tiles of 16. 256 threads.
// Thread (ty=tid/16, tx=tid%16): rows ty*8..ty*8+7, cols {32*i + 2*tx + e}.
// Accumulators packed as f32x2 over (j even, j odd) pairs. Each lane of the
// f32x2 accumulator is a pure ascending-k sequential fma chain from 0 —
// bit-identical to cublas SGEMM's per-thread accumulation.
__global__ __launch_bounds__(256, 2)
void argmin_kernel(const float* __restrict__ z, const float* __restrict__ gt,
                   const float* __restrict__ cb, float* __restrict__ out) {
    __shared__ float2 xs[16][128];     // A operand pre-duplicated {v,v} -> LDS.64 broadcast
    __shared__ float  cs[16][132];     // B operand transposed, pad 4 (528B row, 16B-aligned)
    __shared__ float  cbn_s[N_E];

    const int tid = threadIdx.x;
    const int ty = tid >> 4, tx = tid & 15;
    const int src = blockIdx.y;                       // 0 = z, 1 = gt
    const int rowTile = blockIdx.x << 7;              // *128, within one b (4096%128==0)
    const int b    = rowTile >> 12;
    const int rem0 = rowTile & (HW_ - 1);
    const float* __restrict__ x =
        (src ? gt : z) + (size_t)b * CDIM * HW_ + rem0;

#pragma unroll
    for (int i = 0; i < 4; i++) cbn_s[tid + (i << 8)] = g_cbnorm[tid + (i << 8)];

    float xn[8];
#pragma unroll
    for (int r = 0; r < 8; r++)
        xn[r] = g_xnorm[src * NROWS + rowTile + ty * 8 + r];

    __syncthreads();

    float bestv[8];
    int   bestj[8];
#pragma unroll
    for (int r = 0; r < 8; r++) { bestv[r] = 3.0e38f; bestj[r] = 0; }

    for (int jt = 0; jt < 8; jt++) {
        unsigned long long acc[8][4];
#pragma unroll
        for (int r = 0; r < 8; r++)
#pragma unroll
            for (int i = 0; i < 4; i++) acc[r][i] = 0ull;

        for (int kt = 0; kt < 16; kt++) {
            // stage x tile: 128 rows x 16 c's. Coalesced 512B lines per k.
#pragma unroll
            for (int i = 0; i < 2; i++) {
                int q  = tid + (i << 8);          // 0..511 float4s
                int k  = q >> 5;                  // c within tile
                int m4 = (q & 31) << 2;           // row group
                float4 v = *(const float4*)(x + (size_t)(kt * 16 + k) * HW_ + m4);
                xs[k][m4 + 0] = make_float2(v.x, v.x);
                xs[k][m4 + 1] = make_float2(v.y, v.y);
                xs[k][m4 + 2] = make_float2(v.z, v.z);
                xs[k][m4 + 3] = make_float2(v.w, v.w);
            }
            // stage cb tile transposed: 128 codes x 16 c's
#pragma unroll
            for (int i = 0; i < 2; i++) {
                int q  = tid + (i << 8);
                int j  = q >> 2;
                int c4 = (q & 3) << 2;
                float4 v = *(const float4*)(cb + (size_t)(jt * 128 + j) * CDIM + kt * 16 + c4);
                cs[c4 + 0][j] = v.x;
                cs[c4 + 1][j] = v.y;
                cs[c4 + 2][j] = v.z;
                cs[c4 + 3][j] = v.w;
            }
            __syncthreads();
#pragma unroll
            for (int k = 0; k < 16; k++) {
                unsigned long long av[8], bv[4];
#pragma unroll
                for (int r = 0; r < 8; r++)
                    av[r] = *(const unsigned long long*)&xs[k][ty * 8 + r];
#pragma unroll
                for (int i = 0; i < 4; i++)
                    bv[i] = *(const unsigned long long*)&cs[k][(i << 5) + (tx << 1)];
#pragma unroll
                for (int r = 0; r < 8; r++)
#pragma unroll
                    for (int i = 0; i < 4; i++)
                        fma2(acc[r][i], av[r], bv[i]);
            }
            __syncthreads();
        }

        // epilogue: d = (||x||^2 + ||cb||^2) - 2*dot ; running argmin, ascending j.
        // (xn+cbn) - 2*d: FFMA contraction is rounding-identical (2*d exact).
#pragma unroll
        for (int r = 0; r < 8; r++) {
#pragma unroll
            for (int i = 0; i < 4; i++) {
                float d0, d1;
                upk2(d0, d1, acc[r][i]);
                int jloc = (i << 5) + (tx << 1);
                int jg   = (jt << 7) + jloc;
                float dist0 = (xn[r] + cbn_s[jg])     - 2.0f * d0;
                float dist1 = (xn[r] + cbn_s[jg + 1]) - 2.0f * d1;
                if (dist0 < bestv[r]) { bestv[r] = dist0; bestj[r] = jg; }
                if (dist1 < bestv[r]) { bestv[r] = dist1; bestj[r] = jg + 1; }
            }
        }
    }

    // reduce across the 16 tx lanes (xor<16 stays inside each half-warp).
    // Tie-break: smaller j wins (jnp.argmin = first occurrence).
#pragma unroll
    for (int off = 1; off < 16; off <<= 1) {
#pragma unroll
        for (int r = 0; r < 8; r++) {
            float ov = __shfl_xor_sync(0xffffffffu, bestv[r], off);
            int   oj = __shfl_xor_sync(0xffffffffu, bestj[r], off);
            if (ov < bestv[r] || (ov == bestv[r] && oj < bestj[r])) {
                bestv[r] = ov; bestj[r] = oj;
            }
        }
    }
    if (tx == 0) {
        float* dst = out + (src ? OFF_IDXGT : OFF_IDX);
#pragma unroll
        for (int r = 0; r < 8; r++)
            dst[rowTile + ty * 8 + r] = (float)bestj[r];
    }
}

// ---------- kernel 4: gather + cosine over H ----------
// out[b][w][c] = sum_h qgt*q / (max(||qgt||,eps)*max(||q||,eps)), reduce over h.
// Products rounded separately (mul then add) to track the reference's eager
// elementwise-then-reduce structure; division/sqrt in IEEE rn.
__global__ void cosine_kernel(const float* __restrict__ cb, float* __restrict__ out) {
    int bw = blockIdx.x;          // 0..1023
    int b  = bw >> 6;
    int w  = bw & 63;
    int c  = threadIdx.x;         // 0..255
    __shared__ int i1s[64], i2s[64];
    const float* f_gt = out + OFF_IDXGT;
    const float* f_z  = out + OFF_IDX;
    if (c < 64) {
        int n = (b << 12) + (c << 6) + w;   // c plays the role of h here
        i1s[c] = (int)f_gt[n];
        i2s[c] = (int)f_z[n];
    }
    __syncthreads();
    float num = 0.f, na = 0.f, nq = 0.f;
    for (int h = 0; h < 64; h++) {
        float a = cb[(size_t)i1s[h] * CDIM + c];
        float q = cb[(size_t)i2s[h] * CDIM + c];
        num = __fadd_rn(num, __fmul_rn(a, q));
        na  = __fadd_rn(na,  __fmul_rn(a, a));
        nq  = __fadd_rn(nq,  __fmul_rn(q, q));
    }
    float nx = fmaxf(__fsqrt_rn(na), 1e-8f);
    float ny = fmaxf(__fsqrt_rn(nq), 1e-8f);
    out[(size_t)bw * CDIM + c] = __fdiv_rn(num, __fmul_rn(nx, ny));
}

extern "C" void kernel_launch(void* const* d_in, const int* in_sizes, int n_in,
                              void* d_out, int out_size) {
    const float* z  = (const float*)d_in[0];
    const float* gt = (const float*)d_in[1];
    const float* cb = (const float*)d_in[2];
    float* out = (float*)d_out;

    cbnorm_kernel<<<128, 256>>>(cb);
    xnorm_kernel<<<4096, 1024>>>(z, gt);
    argmin_kernel<<<dim3(512, 2), 256>>>(z, gt, cb, out);
    cosine_kernel<<<NB * NW, CDIM>>>(cb, out);
}

// round 8
// speedup vs baseline: 1.1844x; 1.1844x over previous
#include <cuda_runtime.h>
#include <cstdint>
#include <cstddef>

// Problem constants
#define N_E   1024
#define CDIM  256
#define NB    16
#define NH    64
#define NW    64
#define HW_   (NH*NW)        // 4096
#define NROWS (NB*HW_)       // 65536
#define COS_ELEMS (NB*NW*CDIM)  // 262144

// Output layout (float32): [cosine (B,W,C) | idx_gt (N) | idx (N)]
#define OFF_IDXGT COS_ELEMS
#define OFF_IDX   (COS_ELEMS + NROWS)

// Scratch (device globals: allocation-free rule)
__device__ float g_cbnorm[N_E];
__device__ float g_xnorm[2 * NROWS];

// ---------- packed f32x2 helpers (sm_100+) ----------
static __device__ __forceinline__ void upk2(float& lo, float& hi, unsigned long long v) {
    asm("mov.b64 {%0,%1}, %2;" : "=f"(lo), "=f"(hi) : "l"(v));
}
static __device__ __forceinline__ void pk2(unsigned long long& d, float lo, float hi) {
    asm("mov.b64 %0, {%1,%2};" : "=l"(d) : "f"(lo), "f"(hi));
}
static __device__ __forceinline__ void dup2(unsigned long long& d, float v) {
    asm("mov.b64 %0, {%1,%1};" : "=l"(d) : "f"(v));
}
static __device__ __forceinline__ void fma2(unsigned long long& d,
                                            unsigned long long a,
                                            unsigned long long b) {
    asm("fma.rn.f32x2 %0, %1, %2, %3;" : "=l"(d) : "l"(a), "l"(b), "l"(d));
}

// ---------- XLA-row-reduce-emulating sum of squares over 256 elements ----------
// (unchanged from R3 — this bracketing is what makes argmins match the reference)
template <int STRIDE>
static __device__ __forceinline__ float xla_row_sumsq(const float* __restrict__ p, int lane) {
    float T[4];
#pragma unroll
    for (int w = 0; w < 4; w++) {
        int c0 = w * 64 + 2 * lane;
        float a = p[(size_t)c0 * STRIDE];
        float b = p[(size_t)(c0 + 1) * STRIDE];
        float v = __fadd_rn(__fmul_rn(a, a), __fmul_rn(b, b));
#pragma unroll
        for (int off = 16; off > 0; off >>= 1)
            v = __fadd_rn(v, __shfl_xor_sync(0xffffffffu, v, off));
        T[w] = v;
    }
    return __fadd_rn(__fadd_rn(T[0], T[2]), __fadd_rn(T[1], T[3]));
}

// ---------- kernel 1: codebook squared norms ----------
__global__ void cbnorm_kernel(const float* __restrict__ cb) {
    int warp = blockIdx.x * (blockDim.x >> 5) + (threadIdx.x >> 5);
    int lane = threadIdx.x & 31;
    if (warp >= N_E) return;
    float s = xla_row_sumsq<1>(cb + (size_t)warp * CDIM, lane);
    if (lane == 0) g_cbnorm[warp] = s;
}

// ---------- kernel 2: per-row ||x||^2 for z and gt ----------
__global__ __launch_bounds__(1024)
void xnorm_kernel(const float* __restrict__ z, const float* __restrict__ gt) {
    int wg   = blockIdx.x * 32 + (threadIdx.x >> 5);   // 0..131071
    int lane = threadIdx.x & 31;
    int src  = wg >> 16;
    int n    = wg & (NROWS - 1);
    int b    = n >> 12;
    int rem  = n & (HW_ - 1);
    const float* p = (src ? gt : z) + (size_t)b * CDIM * HW_ + rem;
    float s = xla_row_sumsq<HW_>(p, lane);
    if (lane == 0) g_xnorm[wg] = s;
}

// ---------- kernel 3: fused distance-GEMM + argmin ----------
// BM=128 rows x BN=128 codes per block, K tiles of 16. 256 threads, 2 blocks/SM.
// f32x2 packing over ROW pairs: A pairs are natural (contiguous rows, no dup),
// B is plain f32 in SMEM, duplicated per-use via mov.b64 {b,b} on the ALU pipe.
// Depth-2 software pipeline with REGISTER staging (no cp.async): after each
// __syncthreads, every thread issues its 4 LDG.128s for stage kt+1; they are
// committed to SMEM at the top of kt+1, so L2/GMEM latency hides under the
// 512-FMA2 compute body. One sync per kt; commits at kt touch buf_kt while
// stragglers from kt-1 read buf_kt^1 (disjoint) -> race-free.
// Every accumulator lane is a pure ascending-k sequential fma.rn chain from 0
// -> distances bit-identical to the R3 passing kernel.
__global__ __launch_bounds__(256, 2)
void argmin_kernel(const float* __restrict__ z, const float* __restrict__ gt,
                   const float* __restrict__ cb, float* __restrict__ out) {
    __shared__ float4 xs4[2][16][32];     // [buf][k][row/4]  8KB per buf
    __shared__ float  cs[2][16][132];     // [buf][k][j] plain, pad->528B rows
    __shared__ float  cbn_s[N_E];

    const int tid = threadIdx.x;
    const int ty = tid >> 4, tx = tid & 15;          // ty: row group, tx: j lane
    const int src = blockIdx.y;                      // 0 = z, 1 = gt
    const int rowTile = blockIdx.x << 7;             // *128 (4096%128==0)
    const int b    = rowTile >> 12;
    const int rem0 = rowTile & (HW_ - 1);
    const float* __restrict__ x =
        (src ? gt : z) + (size_t)b * CDIM * HW_ + rem0;

#pragma unroll
    for (int i = 0; i < 4; i++) cbn_s[tid + (i << 8)] = g_cbnorm[tid + (i << 8)];

    float xn[8];
#pragma unroll
    for (int r = 0; r < 8; r++)
        xn[r] = g_xnorm[src * NROWS + rowTile + ty * 8 + r];

    // x-tile staging map: 512 float4 chunks per stage; thread handles chunks
    // tid and tid+256. chunk c -> k = c>>5 (0..15), m = c&31 (float4 col).
    const int k0 = tid >> 5;                  // 0..7  (chunk tid)
    const int m0 = tid & 31;                  //       (chunk tid+256 -> k0+8, same m0)
    const float* xp0 = x + (size_t)k0 * HW_ + (m0 << 2);
    const float* xp1 = x + (size_t)(k0 + 8) * HW_ + (m0 << 2);

    // cb staging map: thread loads j = jl0 (+64) at columns c4..c4+3
    const int jl0 = tid >> 2;                 // 0..63
    const int c4  = (tid & 3) << 2;           // 0,4,8,12
    const float* cbp0 = cb + (size_t)jl0 * CDIM + c4;

    __syncthreads();

    float bestv[8];
    int   bestj[8];
#pragma unroll
    for (int r = 0; r < 8; r++) { bestv[r] = 3.0e38f; bestj[r] = 0; }

    for (int jt = 0; jt < 8; jt++) {
        unsigned long long acc[4][8];
#pragma unroll
        for (int p = 0; p < 4; p++)
#pragma unroll
            for (int q = 0; q < 8; q++) acc[p][q] = 0ull;

        const float* cbp = cbp0 + (size_t)(jt * 128) * CDIM;

        // prologue: stage kt=0 into registers
        float4 xreg0 = *(const float4*)(xp0);
        float4 xreg1 = *(const float4*)(xp1);
        float4 creg0 = *(const float4*)(cbp);
        float4 creg1 = *(const float4*)(cbp + 64 * CDIM);

        for (int kt = 0; kt < 16; kt++) {
            const int buf = kt & 1;
            // commit staged registers to smem[buf]
            xs4[buf][k0][m0]     = xreg0;
            xs4[buf][k0 + 8][m0] = xreg1;
            cs[buf][c4 + 0][jl0]      = creg0.x;
            cs[buf][c4 + 1][jl0]      = creg0.y;
            cs[buf][c4 + 2][jl0]      = creg0.z;
            cs[buf][c4 + 3][jl0]      = creg0.w;
            cs[buf][c4 + 0][jl0 + 64] = creg1.x;
            cs[buf][c4 + 1][jl0 + 64] = creg1.y;
            cs[buf][c4 + 2][jl0 + 64] = creg1.z;
            cs[buf][c4 + 3][jl0 + 64] = creg1.w;
            __syncthreads();
            if (kt < 15) {                   // prefetch kt+1 (overlaps compute)
                const int kb = (kt + 1) * 16;
                xreg0 = *(const float4*)(xp0 + (size_t)kb * HW_);
                xreg1 = *(const float4*)(xp1 + (size_t)kb * HW_);
                creg0 = *(const float4*)(cbp + (size_t)(kt + 1) * 16);
                creg1 = *(const float4*)(cbp + 64 * CDIM + (size_t)(kt + 1) * 16);
            }
#pragma unroll
            for (int k = 0; k < 16; k++) {
                float4 a0 = xs4[buf][k][2 * ty];       // rows 8ty..8ty+3 (broadcast)
                float4 a1 = xs4[buf][k][2 * ty + 1];   // rows 8ty+4..8ty+7
                unsigned long long av[4];
                pk2(av[0], a0.x, a0.y);
                pk2(av[1], a0.z, a0.w);
                pk2(av[2], a1.x, a1.y);
                pk2(av[3], a1.z, a1.w);
#pragma unroll
                for (int qq = 0; qq < 2; qq++) {
                    float4 b4 = *(const float4*)&cs[buf][k][(tx << 2) + (qq << 6)];
#pragma unroll
                    for (int e = 0; e < 4; e++) {
                        unsigned long long bp;
                        dup2(bp, (&b4.x)[e]);
#pragma unroll
                        for (int p = 0; p < 4; p++)
                            fma2(acc[p][(qq << 2) + e], av[p], bp);
                    }
                }
            }
        }

        // epilogue: dist = (||x||^2 + ||cb||^2) - 2*dot; running argmin.
        // Scan order ascending j within thread: qq then e.
#pragma unroll
        for (int qq = 0; qq < 2; qq++)
#pragma unroll
            for (int e = 0; e < 4; e++) {
                const int jg = (jt << 7) + (qq << 6) + (tx << 2) + e;
                const float cbn = cbn_s[jg];
#pragma unroll
                for (int p = 0; p < 4; p++) {
                    float d0, d1;
                    upk2(d0, d1, acc[p][(qq << 2) + e]);
                    const int r0 = 2 * p, r1 = 2 * p + 1;
                    float dist0 = (xn[r0] + cbn) - 2.0f * d0;
                    float dist1 = (xn[r1] + cbn) - 2.0f * d1;
                    if (dist0 < bestv[r0]) { bestv[r0] = dist0; bestj[r0] = jg; }
                    if (dist1 < bestv[r1]) { bestv[r1] = dist1; bestj[r1] = jg; }
                }
            }
        __syncthreads();   // protect smem[buf 15] from next jt's prologue commits
    }

    // reduce across the 16 tx lanes (xor<16 stays inside each half-warp).
    // Tie-break: smaller j wins (jnp.argmin = first occurrence).
#pragma unroll
    for (int off = 1; off < 16; off <<= 1) {
#pragma unroll
        for (int r = 0; r < 8; r++) {
            float ov = __shfl_xor_sync(0xffffffffu, bestv[r], off);
            int   oj = __shfl_xor_sync(0xffffffffu, bestj[r], off);
            if (ov < bestv[r] || (ov == bestv[r] && oj < bestj[r])) {
                bestv[r] = ov; bestj[r] = oj;
            }
        }
    }
    if (tx == 0) {
        float* dst = out + (src ? OFF_IDXGT : OFF_IDX);
#pragma unroll
        for (int r = 0; r < 8; r++)
            dst[rowTile + ty * 8 + r] = (float)bestj[r];
    }
}

// ---------- kernel 4: gather + cosine over H (unchanged) ----------
__global__ void cosine_kernel(const float* __restrict__ cb, float* __restrict__ out) {
    int bw = blockIdx.x;          // 0..1023
    int b  = bw >> 6;
    int w  = bw & 63;
    int c  = threadIdx.x;         // 0..255
    __shared__ int i1s[64], i2s[64];
    const float* f_gt = out + OFF_IDXGT;
    const float* f_z  = out + OFF_IDX;
    if (c < 64) {
        int n = (b << 12) + (c << 6) + w;   // c plays the role of h here
        i1s[c] = (int)f_gt[n];
        i2s[c] = (int)f_z[n];
    }
    __syncthreads();
    float num = 0.f, na = 0.f, nq = 0.f;
    for (int h = 0; h < 64; h++) {
        float a = cb[(size_t)i1s[h] * CDIM + c];
        float q = cb[(size_t)i2s[h] * CDIM + c];
        num = __fadd_rn(num, __fmul_rn(a, q));
        na  = __fadd_rn(na,  __fmul_rn(a, a));
        nq  = __fadd_rn(nq,  __fmul_rn(q, q));
    }
    float nx = fmaxf(__fsqrt_rn(na), 1e-8f);
    float ny = fmaxf(__fsqrt_rn(nq), 1e-8f);
    out[(size_t)bw * CDIM + c] = __fdiv_rn(num, __fmul_rn(nx, ny));
}

extern "C" void kernel_launch(void* const* d_in, const int* in_sizes, int n_in,
                              void* d_out, int out_size) {
    const float* z  = (const float*)d_in[0];
    const float* gt = (const float*)d_in[1];
    const float* cb = (const float*)d_in[2];
    float* out = (float*)d_out;

    cbnorm_kernel<<<128, 256>>>(cb);
    xnorm_kernel<<<4096, 1024>>>(z, gt);
    argmin_kernel<<<dim3(512, 2), 256>>>(z, gt, cb, out);
    cosine_kernel<<<NB * NW, CDIM>>>(cb, out);
}

// round 9
// speedup vs baseline: 1.2097x; 1.0214x over previous
#include <cuda_runtime.h>
#include <cstdint>
#include <cstddef>

// Problem constants
#define N_E   1024
#define CDIM  256
#define NB    16
#define NH    64
#define NW    64
#define HW_   (NH*NW)        // 4096
#define NROWS (NB*HW_)       // 65536
#define COS_ELEMS (NB*NW*CDIM)  // 262144

// Output layout (float32): [cosine (B,W,C) | idx_gt (N) | idx (N)]
#define OFF_IDXGT COS_ELEMS
#define OFF_IDX   (COS_ELEMS + NROWS)

// Scratch (device globals: allocation-free rule)
__device__ float g_cbnorm[N_E];
__device__ float g_xnorm[2 * NROWS];
__device__ float g_bv[2][2][NROWS];   // [src][jhalf][row] partial best dist
__device__ int   g_bj[2][2][NROWS];   // [src][jhalf][row] partial best idx

// ---------- packed f32x2 helpers (sm_100+) ----------
static __device__ __forceinline__ void upk2(float& lo, float& hi, unsigned long long v) {
    asm("mov.b64 {%0,%1}, %2;" : "=f"(lo), "=f"(hi) : "l"(v));
}
static __device__ __forceinline__ void dup2(unsigned long long& d, float v) {
    asm("mov.b64 %0, {%1,%1};" : "=l"(d) : "f"(v));
}
static __device__ __forceinline__ void fma2(unsigned long long& d,
                                            unsigned long long a,
                                            unsigned long long b) {
    asm("fma.rn.f32x2 %0, %1, %2, %3;" : "=l"(d) : "l"(a), "l"(b), "l"(d));
}

// ---------- XLA-row-reduce-emulating sum of squares over 256 elements ----------
// (unchanged — this bracketing is what makes argmins match the reference)
template <int STRIDE>
static __device__ __forceinline__ float xla_row_sumsq(const float* __restrict__ p, int lane) {
    float T[4];
#pragma unroll
    for (int w = 0; w < 4; w++) {
        int c0 = w * 64 + 2 * lane;
        float a = p[(size_t)c0 * STRIDE];
        float b = p[(size_t)(c0 + 1) * STRIDE];
        float v = __fadd_rn(__fmul_rn(a, a), __fmul_rn(b, b));
#pragma unroll
        for (int off = 16; off > 0; off >>= 1)
            v = __fadd_rn(v, __shfl_xor_sync(0xffffffffu, v, off));
        T[w] = v;
    }
    return __fadd_rn(__fadd_rn(T[0], T[2]), __fadd_rn(T[1], T[3]));
}

// ---------- kernel 1: codebook squared norms ----------
__global__ void cbnorm_kernel(const float* __restrict__ cb) {
    int warp = blockIdx.x * (blockDim.x >> 5) + (threadIdx.x >> 5);
    int lane = threadIdx.x & 31;
    if (warp >= N_E) return;
    float s = xla_row_sumsq<1>(cb + (size_t)warp * CDIM, lane);
    if (lane == 0) g_cbnorm[warp] = s;
}

// ---------- kernel 2: per-row ||x||^2 for z and gt ----------
__global__ __launch_bounds__(1024)
void xnorm_kernel(const float* __restrict__ z, const float* __restrict__ gt) {
    int wg   = blockIdx.x * 32 + (threadIdx.x >> 5);   // 0..131071
    int lane = threadIdx.x & 31;
    int src  = wg >> 16;
    int n    = wg & (NROWS - 1);
    int b    = n >> 12;
    int rem  = n & (HW_ - 1);
    const float* p = (src ? gt : z) + (size_t)b * CDIM * HW_ + rem;
    float s = xla_row_sumsq<HW_>(p, lane);
    if (lane == 0) g_xnorm[wg] = s;
}

// ---------- kernel 3: fused distance-GEMM + partial argmin ----------
// BM=128 rows x BN=128 codes, K tiles of 16, 256 threads, 2 blocks/SM.
// blockIdx.z = jhalf: each block covers 4 jt tiles (512 codes) -> 2048 equal
// blocks -> 6.92 waves at 296-CTA residency (98.9% wave efficiency vs 86.5%
// at 1024 blocks). Partial (bestv,bestj) per row goes to global scratch;
// combine_kernel merges halves (ties -> low half = smaller j).
// f32x2 over ROW pairs; A loaded as ulonglong2 (LDS.128 dest pairs used
// directly as 64-bit FMA2 operands -> no pack MOVs); B scalar in SMEM,
// duplicated per-use via mov.b64 {b,b}. Register-staged depth-2 pipeline.
// Accumulator lanes: pure ascending-k sequential fma.rn chains from 0 ->
// distances bit-identical to the R3/R8 passing kernels.
__global__ __launch_bounds__(256, 2)
void argmin_kernel(const float* __restrict__ z, const float* __restrict__ gt,
                   const float* __restrict__ cb) {
    __shared__ float4 xs4[2][16][32];     // [buf][k][row/4]  8KB per buf
    __shared__ float  cs[2][16][132];     // [buf][k][j] plain, pad->528B rows
    __shared__ float  cbn_s[512];         // this half's codebook norms

    const int tid = threadIdx.x;
    const int ty = tid >> 4, tx = tid & 15;          // ty: row group, tx: j lane
    const int src = blockIdx.y;                      // 0 = z, 1 = gt
    const int jh  = blockIdx.z;                      // j half: codes [jh*512, jh*512+512)
    const int rowTile = blockIdx.x << 7;             // *128 (4096%128==0)
    const int b    = rowTile >> 12;
    const int rem0 = rowTile & (HW_ - 1);
    const float* __restrict__ x =
        (src ? gt : z) + (size_t)b * CDIM * HW_ + rem0;

#pragma unroll
    for (int i = 0; i < 2; i++)
        cbn_s[tid + (i << 8)] = g_cbnorm[(jh << 9) + tid + (i << 8)];

    float xn[8];
#pragma unroll
    for (int r = 0; r < 8; r++)
        xn[r] = g_xnorm[src * NROWS + rowTile + ty * 8 + r];

    // x-tile staging map: 512 float4 chunks per stage; thread handles chunks
    // tid and tid+256. chunk c -> k = c>>5 (0..15), m = c&31 (float4 col).
    const int k0 = tid >> 5;                  // 0..7  (chunk tid)
    const int m0 = tid & 31;                  //       (chunk tid+256 -> k0+8, same m0)
    const float* xp0 = x + (size_t)k0 * HW_ + (m0 << 2);
    const float* xp1 = x + (size_t)(k0 + 8) * HW_ + (m0 << 2);

    // cb staging map: thread loads j = jl0 (+64) at columns c4..c4+3
    const int jl0 = tid >> 2;                 // 0..63
    const int c4  = (tid & 3) << 2;           // 0,4,8,12
    const float* cbp0 = cb + (size_t)((jh << 9) + jl0) * CDIM + c4;

    __syncthreads();

    float bestv[8];
    int   bestj[8];
#pragma unroll
    for (int r = 0; r < 8; r++) { bestv[r] = 3.0e38f; bestj[r] = 0; }

    for (int jt = 0; jt < 4; jt++) {
        unsigned long long acc[4][8];
#pragma unroll
        for (int p = 0; p < 4; p++)
#pragma unroll
            for (int q = 0; q < 8; q++) acc[p][q] = 0ull;

        const float* cbp = cbp0 + (size_t)(jt * 128) * CDIM;

        // prologue: stage kt=0 into registers
        float4 xreg0 = *(const float4*)(xp0);
        float4 xreg1 = *(const float4*)(xp1);
        float4 creg0 = *(const float4*)(cbp);
        float4 creg1 = *(const float4*)(cbp + 64 * CDIM);

        for (int kt = 0; kt < 16; kt++) {
            const int buf = kt & 1;
            // commit staged registers to smem[buf]
            xs4[buf][k0][m0]     = xreg0;
            xs4[buf][k0 + 8][m0] = xreg1;
            cs[buf][c4 + 0][jl0]      = creg0.x;
            cs[buf][c4 + 1][jl0]      = creg0.y;
            cs[buf][c4 + 2][jl0]      = creg0.z;
            cs[buf][c4 + 3][jl0]      = creg0.w;
            cs[buf][c4 + 0][jl0 + 64] = creg1.x;
            cs[buf][c4 + 1][jl0 + 64] = creg1.y;
            cs[buf][c4 + 2][jl0 + 64] = creg1.z;
            cs[buf][c4 + 3][jl0 + 64] = creg1.w;
            __syncthreads();
            if (kt < 15) {                   // prefetch kt+1 (overlaps compute)
                const int kb = (kt + 1) * 16;
                xreg0 = *(const float4*)(xp0 + (size_t)kb * HW_);
                xreg1 = *(const float4*)(xp1 + (size_t)kb * HW_);
                creg0 = *(const float4*)(cbp + (size_t)(kt + 1) * 16);
                creg1 = *(const float4*)(cbp + 64 * CDIM + (size_t)(kt + 1) * 16);
            }
#pragma unroll
            for (int k = 0; k < 16; k++) {
                // A: rows 8ty..8ty+7 as 4 natural f32x2 pairs (no pack MOVs)
                ulonglong2 u0 = *(const ulonglong2*)&xs4[buf][k][2 * ty];
                ulonglong2 u1 = *(const ulonglong2*)&xs4[buf][k][2 * ty + 1];
                unsigned long long av[4];
                av[0] = u0.x; av[1] = u0.y; av[2] = u1.x; av[3] = u1.y;
#pragma unroll
                for (int qq = 0; qq < 2; qq++) {
                    float4 b4 = *(const float4*)&cs[buf][k][(tx << 2) + (qq << 6)];
#pragma unroll
                    for (int e = 0; e < 4; e++) {
                        unsigned long long bp;
                        dup2(bp, (&b4.x)[e]);
#pragma unroll
                        for (int p = 0; p < 4; p++)
                            fma2(acc[p][(qq << 2) + e], av[p], bp);
                    }
                }
            }
        }

        // epilogue: dist = (||x||^2 + ||cb||^2) - 2*dot; running argmin.
#pragma unroll
        for (int qq = 0; qq < 2; qq++)
#pragma unroll
            for (int e = 0; e < 4; e++) {
                const int jloc = (jt << 7) + (qq << 6) + (tx << 2) + e;
                const int jg   = (jh << 9) + jloc;
                const float cbn = cbn_s[jloc];
#pragma unroll
                for (int p = 0; p < 4; p++) {
                    float d0, d1;
                    upk2(d0, d1, acc[p][(qq << 2) + e]);
                    const int r0 = 2 * p, r1 = 2 * p + 1;
                    float dist0 = (xn[r0] + cbn) - 2.0f * d0;
                    float dist1 = (xn[r1] + cbn) - 2.0f * d1;
                    if (dist0 < bestv[r0]) { bestv[r0] = dist0; bestj[r0] = jg; }
                    if (dist1 < bestv[r1]) { bestv[r1] = dist1; bestj[r1] = jg; }
                }
            }
        __syncthreads();   // protect smem[buf 15] from next jt's prologue commits
    }

    // reduce across the 16 tx lanes (xor<16 stays inside each half-warp).
    // Tie-break: smaller j wins (jnp.argmin = first occurrence).
#pragma unroll
    for (int off = 1; off < 16; off <<= 1) {
#pragma unroll
        for (int r = 0; r < 8; r++) {
            float ov = __shfl_xor_sync(0xffffffffu, bestv[r], off);
            int   oj = __shfl_xor_sync(0xffffffffu, bestj[r], off);
            if (ov < bestv[r] || (ov == bestv[r] && oj < bestj[r])) {
                bestv[r] = ov; bestj[r] = oj;
            }
        }
    }
    if (tx == 0) {
#pragma unroll
        for (int r = 0; r < 8; r++) {
            g_bv[src][jh][rowTile + ty * 8 + r] = bestv[r];
            g_bj[src][jh][rowTile + ty * 8 + r] = bestj[r];
        }
    }
}

// ---------- kernel 3b: merge the two j-halves ----------
// Strict <: on ties the low half wins (its j is smaller) = first occurrence.
__global__ void combine_kernel(float* __restrict__ out) {
    int i = blockIdx.x * blockDim.x + threadIdx.x;   // 0..131071
    int src = i >> 16;
    int n   = i & (NROWS - 1);
    float v0 = g_bv[src][0][n];
    float v1 = g_bv[src][1][n];
    int   j  = (v1 < v0) ? g_bj[src][1][n] : g_bj[src][0][n];
    out[(src ? OFF_IDXGT : OFF_IDX) + n] = (float)j;
}

// ---------- kernel 4: gather + cosine over H (unchanged) ----------
__global__ void cosine_kernel(const float* __restrict__ cb, float* __restrict__ out) {
    int bw = blockIdx.x;          // 0..1023
    int b  = bw >> 6;
    int w  = bw & 63;
    int c  = threadIdx.x;         // 0..255
    __shared__ int i1s[64], i2s[64];
    const float* f_gt = out + OFF_IDXGT;
    const float* f_z  = out + OFF_IDX;
    if (c < 64) {
        int n = (b << 12) + (c << 6) + w;   // c plays the role of h here
        i1s[c] = (int)f_gt[n];
        i2s[c] = (int)f_z[n];
    }
    __syncthreads();
    float num = 0.f, na = 0.f, nq = 0.f;
    for (int h = 0; h < 64; h++) {
        float a = cb[(size_t)i1s[h] * CDIM + c];
        float q = cb[(size_t)i2s[h] * CDIM + c];
        num = __fadd_rn(num, __fmul_rn(a, q));
        na  = __fadd_rn(na,  __fmul_rn(a, a));
        nq  = __fadd_rn(nq,  __fmul_rn(q, q));
    }
    float nx = fmaxf(__fsqrt_rn(na), 1e-8f);
    float ny = fmaxf(__fsqrt_rn(nq), 1e-8f);
    out[(size_t)bw * CDIM + c] = __fdiv_rn(num, __fmul_rn(nx, ny));
}

extern "C" void kernel_launch(void* const* d_in, const int* in_sizes, int n_in,
                              void* d_out, int out_size) {
    const float* z  = (const float*)d_in[0];
    const float* gt = (const float*)d_in[1];
    const float* cb = (const float*)d_in[2];
    float* out = (float*)d_out;

    cbnorm_kernel<<<128, 256>>>(cb);
    xnorm_kernel<<<4096, 1024>>>(z, gt);
    argmin_kernel<<<dim3(512, 2, 2), 256>>>(z, gt, cb);
    combine_kernel<<<128, 1024>>>(out);
    cosine_kernel<<<NB * NW, CDIM>>>(cb, out);
}

// round 10
// speedup vs baseline: 1.2875x; 1.0643x over previous
#include <cuda_runtime.h>
#include <cstdint>
#include <cstddef>

// Problem constants
#define N_E   1024
#define CDIM  256
#define NB    16
#define NH    64
#define NW    64
#define HW_   (NH*NW)        // 4096
#define NROWS (NB*HW_)       // 65536
#define COS_ELEMS (NB*NW*CDIM)  // 262144

// Output layout (float32): [cosine (B,W,C) | idx_gt (N) | idx (N)]
#define OFF_IDXGT COS_ELEMS
#define OFF_IDX   (COS_ELEMS + NROWS)

// Scratch (device globals: allocation-free rule)
__device__ float g_cbnorm[N_E];
__device__ float g_xnorm[2 * NROWS];
__device__ float g_bv[2][2][NROWS];   // [src][jhalf][row] partial best dist
__device__ int   g_bj[2][2][NROWS];   // [src][jhalf][row] partial best idx

// ---------- packed f32x2 helpers (sm_100+) ----------
static __device__ __forceinline__ void upk2(float& lo, float& hi, unsigned long long v) {
    asm("mov.b64 {%0,%1}, %2;" : "=f"(lo), "=f"(hi) : "l"(v));
}
static __device__ __forceinline__ void dup2(unsigned long long& d, float v) {
    asm("mov.b64 %0, {%1,%1};" : "=l"(d) : "f"(v));
}
static __device__ __forceinline__ void fma2(unsigned long long& d,
                                            unsigned long long a,
                                            unsigned long long b) {
    asm("fma.rn.f32x2 %0, %1, %2, %3;" : "=l"(d) : "l"(a), "l"(b), "l"(d));
}

// ---------- XLA-row-reduce-emulating sum of squares over 256 elements ----------
// (unchanged — this bracketing is what makes argmins match the reference)
template <int STRIDE>
static __device__ __forceinline__ float xla_row_sumsq(const float* __restrict__ p, int lane) {
    float T[4];
#pragma unroll
    for (int w = 0; w < 4; w++) {
        int c0 = w * 64 + 2 * lane;
        float a = p[(size_t)c0 * STRIDE];
        float b = p[(size_t)(c0 + 1) * STRIDE];
        float v = __fadd_rn(__fmul_rn(a, a), __fmul_rn(b, b));
#pragma unroll
        for (int off = 16; off > 0; off >>= 1)
            v = __fadd_rn(v, __shfl_xor_sync(0xffffffffu, v, off));
        T[w] = v;
    }
    return __fadd_rn(__fadd_rn(T[0], T[2]), __fadd_rn(T[1], T[3]));
}

// ---------- kernel 1: codebook squared norms ----------
__global__ void cbnorm_kernel(const float* __restrict__ cb) {
    int warp = blockIdx.x * (blockDim.x >> 5) + (threadIdx.x >> 5);
    int lane = threadIdx.x & 31;
    if (warp >= N_E) return;
    float s = xla_row_sumsq<1>(cb + (size_t)warp * CDIM, lane);
    if (lane == 0) g_cbnorm[warp] = s;
}

// ---------- kernel 2: per-row ||x||^2, coalesced via SMEM transpose ----------
// Block = 32 consecutive rows x 256 c. Each warp reads 32 consecutive n at
// fixed c (128B coalesced), stores to ts[n][c] (row stride 257 -> conflict-
// free). Then warp w reduces rows 4w..4w+3 from SMEM with the IDENTICAL
// xla_row_sumsq bracketing -> g_xnorm bit-identical to previous rounds.
__global__ __launch_bounds__(256)
void xnorm_kernel(const float* __restrict__ x, int src) {
    __shared__ float ts[32][257];
    const int n0  = blockIdx.x << 5;          // 2048 blocks per source
    const int b   = n0 >> 12;
    const int rem = n0 & (HW_ - 1);
    const float* base = x + (size_t)b * CDIM * HW_ + rem;
    const int w = threadIdx.x >> 5, l = threadIdx.x & 31;
#pragma unroll
    for (int i = 0; i < 32; i++) {
        int c = w + (i << 3);                 // warp w covers c = w, w+8, ...
        ts[l][c] = base[(size_t)c * HW_ + l];
    }
    __syncthreads();
#pragma unroll
    for (int r = 0; r < 4; r++) {
        int row = (w << 2) + r;
        float s = xla_row_sumsq<1>(&ts[row][0], l);
        if (l == 0) g_xnorm[src * NROWS + n0 + row] = s;
    }
}

// ---------- kernel 3: fused distance-GEMM + partial argmin (unchanged R9) ----------
__global__ __launch_bounds__(256, 2)
void argmin_kernel(const float* __restrict__ z, const float* __restrict__ gt,
                   const float* __restrict__ cb) {
    __shared__ float4 xs4[2][16][32];     // [buf][k][row/4]  8KB per buf
    __shared__ float  cs[2][16][132];     // [buf][k][j] plain, pad->528B rows
    __shared__ float  cbn_s[512];         // this half's codebook norms

    const int tid = threadIdx.x;
    const int ty = tid >> 4, tx = tid & 15;          // ty: row group, tx: j lane
    const int src = blockIdx.y;                      // 0 = z, 1 = gt
    const int jh  = blockIdx.z;                      // j half: codes [jh*512, jh*512+512)
    const int rowTile = blockIdx.x << 7;             // *128 (4096%128==0)
    const int b    = rowTile >> 12;
    const int rem0 = rowTile & (HW_ - 1);
    const float* __restrict__ x =
        (src ? gt : z) + (size_t)b * CDIM * HW_ + rem0;

#pragma unroll
    for (int i = 0; i < 2; i++)
        cbn_s[tid + (i << 8)] = g_cbnorm[(jh << 9) + tid + (i << 8)];

    float xn[8];
#pragma unroll
    for (int r = 0; r < 8; r++)
        xn[r] = g_xnorm[src * NROWS + rowTile + ty * 8 + r];

    // x-tile staging map: 512 float4 chunks per stage; thread handles chunks
    // tid and tid+256. chunk c -> k = c>>5 (0..15), m = c&31 (float4 col).
    const int k0 = tid >> 5;                  // 0..7  (chunk tid)
    const int m0 = tid & 31;                  //       (chunk tid+256 -> k0+8, same m0)
    const float* xp0 = x + (size_t)k0 * HW_ + (m0 << 2);
    const float* xp1 = x + (size_t)(k0 + 8) * HW_ + (m0 << 2);

    // cb staging map: thread loads j = jl0 (+64) at columns c4..c4+3
    const int jl0 = tid >> 2;                 // 0..63
    const int c4  = (tid & 3) << 2;           // 0,4,8,12
    const float* cbp0 = cb + (size_t)((jh << 9) + jl0) * CDIM + c4;

    __syncthreads();

    float bestv[8];
    int   bestj[8];
#pragma unroll
    for (int r = 0; r < 8; r++) { bestv[r] = 3.0e38f; bestj[r] = 0; }

    for (int jt = 0; jt < 4; jt++) {
        unsigned long long acc[4][8];
#pragma unroll
        for (int p = 0; p < 4; p++)
#pragma unroll
            for (int q = 0; q < 8; q++) acc[p][q] = 0ull;

        const float* cbp = cbp0 + (size_t)(jt * 128) * CDIM;

        // prologue: stage kt=0 into registers
        float4 xreg0 = *(const float4*)(xp0);
        float4 xreg1 = *(const float4*)(xp1);
        float4 creg0 = *(const float4*)(cbp);
        float4 creg1 = *(const float4*)(cbp + 64 * CDIM);

        for (int kt = 0; kt < 16; kt++) {
            const int buf = kt & 1;
            // commit staged registers to smem[buf]
            xs4[buf][k0][m0]     = xreg0;
            xs4[buf][k0 + 8][m0] = xreg1;
            cs[buf][c4 + 0][jl0]      = creg0.x;
            cs[buf][c4 + 1][jl0]      = creg0.y;
            cs[buf][c4 + 2][jl0]      = creg0.z;
            cs[buf][c4 + 3][jl0]      = creg0.w;
            cs[buf][c4 + 0][jl0 + 64] = creg1.x;
            cs[buf][c4 + 1][jl0 + 64] = creg1.y;
            cs[buf][c4 + 2][jl0 + 64] = creg1.z;
            cs[buf][c4 + 3][jl0 + 64] = creg1.w;
            __syncthreads();
            if (kt < 15) {                   // prefetch kt+1 (overlaps compute)
                const int kb = (kt + 1) * 16;
                xreg0 = *(const float4*)(xp0 + (size_t)kb * HW_);
                xreg1 = *(const float4*)(xp1 + (size_t)kb * HW_);
                creg0 = *(const float4*)(cbp + (size_t)(kt + 1) * 16);
                creg1 = *(const float4*)(cbp + 64 * CDIM + (size_t)(kt + 1) * 16);
            }
#pragma unroll
            for (int k = 0; k < 16; k++) {
                // A: rows 8ty..8ty+7 as 4 natural f32x2 pairs (no pack MOVs)
                ulonglong2 u0 = *(const ulonglong2*)&xs4[buf][k][2 * ty];
                ulonglong2 u1 = *(const ulonglong2*)&xs4[buf][k][2 * ty + 1];
                unsigned long long av[4];
                av[0] = u0.x; av[1] = u0.y; av[2] = u1.x; av[3] = u1.y;
#pragma unroll
                for (int qq = 0; qq < 2; qq++) {
                    float4 b4 = *(const float4*)&cs[buf][k][(tx << 2) + (qq << 6)];
#pragma unroll
                    for (int e = 0; e < 4; e++) {
                        unsigned long long bp;
                        dup2(bp, (&b4.x)[e]);
#pragma unroll
                        for (int p = 0; p < 4; p++)
                            fma2(acc[p][(qq << 2) + e], av[p], bp);
                    }
                }
            }
        }

        // epilogue: dist = (||x||^2 + ||cb||^2) - 2*dot; running argmin.
#pragma unroll
        for (int qq = 0; qq < 2; qq++)
#pragma unroll
            for (int e = 0; e < 4; e++) {
                const int jloc = (jt << 7) + (qq << 6) + (tx << 2) + e;
                const int jg   = (jh << 9) + jloc;
                const float cbn = cbn_s[jloc];
#pragma unroll
                for (int p = 0; p < 4; p++) {
                    float d0, d1;
                    upk2(d0, d1, acc[p][(qq << 2) + e]);
                    const int r0 = 2 * p, r1 = 2 * p + 1;
                    float dist0 = (xn[r0] + cbn) - 2.0f * d0;
                    float dist1 = (xn[r1] + cbn) - 2.0f * d1;
                    if (dist0 < bestv[r0]) { bestv[r0] = dist0; bestj[r0] = jg; }
                    if (dist1 < bestv[r1]) { bestv[r1] = dist1; bestj[r1] = jg; }
                }
            }
        __syncthreads();   // protect smem[buf 15] from next jt's prologue commits
    }

    // reduce across the 16 tx lanes (xor<16 stays inside each half-warp).
    // Tie-break: smaller j wins (jnp.argmin = first occurrence).
#pragma unroll
    for (int off = 1; off < 16; off <<= 1) {
#pragma unroll
        for (int r = 0; r < 8; r++) {
            float ov = __shfl_xor_sync(0xffffffffu, bestv[r], off);
            int   oj = __shfl_xor_sync(0xffffffffu, bestj[r], off);
            if (ov < bestv[r] || (ov == bestv[r] && oj < bestj[r])) {
                bestv[r] = ov; bestj[r] = oj;
            }
        }
    }
    if (tx == 0) {
#pragma unroll
        for (int r = 0; r < 8; r++) {
            g_bv[src][jh][rowTile + ty * 8 + r] = bestv[r];
            g_bj[src][jh][rowTile + ty * 8 + r] = bestj[r];
        }
    }
}

// ---------- kernel 3b: merge the two j-halves ----------
// Strict <: on ties the low half wins (its j is smaller) = first occurrence.
__global__ void combine_kernel(float* __restrict__ out) {
    int i = blockIdx.x * blockDim.x + threadIdx.x;   // 0..131071
    int src = i >> 16;
    int n   = i & (NROWS - 1);
    float v0 = g_bv[src][0][n];
    float v1 = g_bv[src][1][n];
    int   j  = (v1 < v0) ? g_bj[src][1][n] : g_bj[src][0][n];
    out[(src ? OFF_IDXGT : OFF_IDX) + n] = (float)j;
}

// ---------- kernel 4: gather + cosine over H (unchanged) ----------
__global__ void cosine_kernel(const float* __restrict__ cb, float* __restrict__ out) {
    int bw = blockIdx.x;          // 0..1023
    int b  = bw >> 6;
    int w  = bw & 63;
    int c  = threadIdx.x;         // 0..255
    __shared__ int i1s[64], i2s[64];
    const float* f_gt = out + OFF_IDXGT;
    const float* f_z  = out + OFF_IDX;
    if (c < 64) {
        int n = (b << 12) + (c << 6) + w;   // c plays the role of h here
        i1s[c] = (int)f_gt[n];
        i2s[c] = (int)f_z[n];
    }
    __syncthreads();
    float num = 0.f, na = 0.f, nq = 0.f;
    for (int h = 0; h < 64; h++) {
        float a = cb[(size_t)i1s[h] * CDIM + c];
        float q = cb[(size_t)i2s[h] * CDIM + c];
        num = __fadd_rn(num, __fmul_rn(a, q));
        na  = __fadd_rn(na,  __fmul_rn(a, a));
        nq  = __fadd_rn(nq,  __fmul_rn(q, q));
    }
    float nx = fmaxf(__fsqrt_rn(na), 1e-8f);
    float ny = fmaxf(__fsqrt_rn(nq), 1e-8f);
    out[(size_t)bw * CDIM + c] = __fdiv_rn(num, __fmul_rn(nx, ny));
}

extern "C" void kernel_launch(void* const* d_in, const int* in_sizes, int n_in,
                              void* d_out, int out_size) {
    const float* z  = (const float*)d_in[0];
    const float* gt = (const float*)d_in[1];
    const float* cb = (const float*)d_in[2];
    float* out = (float*)d_out;

    cbnorm_kernel<<<128, 256>>>(cb);          // launch 0
    xnorm_kernel<<<2048, 256>>>(z, 0);        // launch 1
    xnorm_kernel<<<2048, 256>>>(gt, 1);       // launch 2
    argmin_kernel<<<dim3(512, 2, 2), 256>>>(z, gt, cb);   // launch 3 (ncu samples idx 3)
    combine_kernel<<<128, 1024>>>(out);       // launch 4
    cosine_kernel<<<NB * NW, CDIM>>>(cb, out);// launch 5
}